// round 14
// baseline (speedup 1.0000x reference)
#include <cuda_runtime.h>
#include <cstdint>
#include <math.h>

#define SEQ   4096
#define EMB   256
#define H     256
#define G4    1024   // 4*H
#define NTAGS 32
#define NCHUNK 64
#define CHUNK  64

// ---------------- scratch (device globals: no allocation allowed) ----------
__device__ float g_gx[2][SEQ][G4];       // input projections per direction
__device__ float g_hs[SEQ][2 * H];       // concatenated BiLSTM hidden states
__device__ float g_em[SEQ][NTAGS];       // emissions (log space)
__device__ float g_eem[SEQ][NTAGS];      // exp(em)  (linear space, UNSCALED)
__device__ float g_chunk[NCHUNK][NTAGS][NTAGS];  // chunk transfer matrices
__device__ float g_chunkL[NCHUNK];               // their log2 scale factors

__device__ __forceinline__ unsigned smem_u32(const void* p) {
    return (unsigned)__cvta_generic_to_shared(p);
}

#define CLUSTER_ARRIVE() \
    asm volatile("barrier.cluster.arrive.aligned;" ::: "memory")
#define CLUSTER_WAIT() \
    asm volatile("barrier.cluster.wait.aligned;"   ::: "memory")
#define CLUSTER_SYNC_ASM() do { CLUSTER_ARRIVE(); CLUSTER_WAIT(); } while (0)

// ============================================================================
// Kernel A: gx[d][t][r] = emb_d[t] . w_ih_d[r] + b_ih[r] + b_hh[r]
// ============================================================================
__global__ void gx_kernel(const float* __restrict__ embed,
                          const float* __restrict__ w_ih_f,
                          const float* __restrict__ b_ih_f,
                          const float* __restrict__ b_hh_f,
                          const float* __restrict__ w_ih_b,
                          const float* __restrict__ b_ih_b,
                          const float* __restrict__ b_hh_b,
                          const int*   __restrict__ x)
{
    const int dir = blockIdx.z;
    const float* w_ih = dir ? w_ih_b : w_ih_f;
    const float* b_ih = dir ? b_ih_b : b_ih_f;
    const float* b_hh = dir ? b_hh_b : b_hh_f;

    __shared__ float As[64][33];
    __shared__ float Bs[64][33];
    __shared__ int   toks[64];

    const int tid = threadIdx.x;
    const int t0 = blockIdx.x * 64;
    const int r0 = blockIdx.y * 64;

    if (tid < 64) {
        int t = t0 + tid;
        int p = dir ? (SEQ - 1 - t) : t;
        toks[tid] = x[p];
    }
    __syncthreads();

    const int tx = tid & 15, ty = tid >> 4;
    float c[4][4] = {};

    for (int k0 = 0; k0 < EMB; k0 += 32) {
        for (int i = tid; i < 64 * 32; i += 256) {
            int row = i >> 5, k = i & 31;
            As[row][k] = embed[(size_t)toks[row] * EMB + k0 + k];
        }
        for (int i = tid; i < 64 * 32; i += 256) {
            int row = i >> 5, k = i & 31;
            Bs[row][k] = w_ih[(size_t)(r0 + row) * EMB + k0 + k];
        }
        __syncthreads();
        #pragma unroll
        for (int kk = 0; kk < 32; kk++) {
            float a[4], b[4];
            #pragma unroll
            for (int u = 0; u < 4; u++) a[u] = As[ty * 4 + u][kk];
            #pragma unroll
            for (int v = 0; v < 4; v++) b[v] = Bs[tx * 4 + v][kk];
            #pragma unroll
            for (int u = 0; u < 4; u++)
                #pragma unroll
                for (int v = 0; v < 4; v++)
                    c[u][v] += a[u] * b[v];
        }
        __syncthreads();
    }

    #pragma unroll
    for (int u = 0; u < 4; u++) {
        int t = t0 + ty * 4 + u;
        #pragma unroll
        for (int v = 0; v < 4; v++) {
            int r = r0 + tx * 4 + v;
            g_gx[dir][t][r] = c[u][v] + b_ih[r] + b_hh[r];
        }
    }
}

// ============================================================================
// Kernel B: sequential BiLSTM recurrence (2 clusters of 8 CTAs).
// R12 compute structure; the per-step HW cluster barrier (UCGABAR_WAIT ~490
// cyc) is replaced by flag-based DSMEM sync:
//   producer: leader warp stores h to all 8 peers, __syncwarp, then lanes
//     0-7 each issue ONE st.release.cluster of a monotone step counter to a
//     DISTINCT flag word in each peer (no atomics -> no serialization, the
//     failure mode of the r5/r10 mbarrier variants).
//   consumer: every warp polls its 8 local flag words with
//     ld.acquire.cluster (LDS-speed, ~29 cyc when ready).
// Safety: flag value t+1 is stored only after that CTA's phase-1 reads of
// step t completed (ordered by its __syncthreads), so the h double-buffer
// tolerates the 1-step skew.  Monotone counters -> no reset/parity races.
// ============================================================================
__global__ void __cluster_dims__(8, 1, 1) __launch_bounds__(512, 1)
lstm_kernel(const float* __restrict__ w_hh_f, const float* __restrict__ w_hh_b)
{
    __shared__ __align__(16) float sh_h[2][256];   // double-buffered h
    __shared__ __align__(16) float red[512];       // float4-grouped partials
    __shared__ unsigned sflag[8];                  // step counters per src CTA

    const int tid = threadIdx.x;
    const int l   = tid & 31;
    const int dir = blockIdx.x >> 3;
    unsigned rank;
    asm("mov.u32 %0, %%cluster_ctarank;" : "=r"(rank));
    const int j0 = (int)rank * 32;

    const float* __restrict__ w_hh = dir ? w_hh_b : w_hh_f;

    const int g    = ((tid >> 7) << 5) | l;           // 0..127 local gate id
    const int s    = (tid >> 5) & 3;                  // 0..3  K slice
    const int gate = g >> 5;                          // i,f,g,o
    const int j    = g & 31;                          // hidden index within CTA
    const int row  = gate * H + j0 + j;               // global gate row

    // ---- weights into registers as packed f32x2 pairs ----
    unsigned long long w2[32];
    {
        const ulonglong2* wv =
            (const ulonglong2*)(w_hh + (size_t)row * H + s * 64);
        #pragma unroll
        for (int q = 0; q < 16; q++) {
            ulonglong2 v = wv[q];
            w2[2 * q] = v.x; w2[2 * q + 1] = v.y;
        }
    }

    if (tid < 256) { sh_h[0][tid] = 0.f; sh_h[1][tid] = 0.f; }
    if (tid < 8)   sflag[tid] = 0u;

    // remote h addresses in two separate register arrays (no LDL)
    unsigned raddr0[8], raddr1[8];
    if (tid < 32) {
        unsigned la0 = smem_u32(&sh_h[0][j0 + tid]);
        unsigned la1 = smem_u32(&sh_h[1][j0 + tid]);
        #pragma unroll
        for (int cc = 0; cc < 8; cc++) {
            asm("mapa.shared::cluster.u32 %0, %1, %2;"
                : "=r"(raddr0[cc]) : "r"(la0), "r"(cc));
            asm("mapa.shared::cluster.u32 %0, %1, %2;"
                : "=r"(raddr1[cc]) : "r"(la1), "r"(cc));
        }
    }
    // remote flag address: lane k signals peer k's sflag[rank]
    unsigned fl_raddr = 0;
    if (tid < 8) {
        unsigned la = smem_u32(&sflag[rank]);
        asm("mapa.shared::cluster.u32 %0, %1, %2;"
            : "=r"(fl_raddr) : "r"(la), "r"(tid));
    }
    const unsigned fl_local = smem_u32(&sflag[l & 7]);

    CLUSTER_SYNC_ASM();   // zeros + flag init visible cluster-wide

    float cstate = 0.f;
    const float* __restrict__ gx_base = &g_gx[dir][0][0];
    const float L2E = 1.4426950408889634f;

    // preload gx for step 0
    float gc0 = 0.f, gc1 = 0.f, gc2 = 0.f, gc3 = 0.f;
    if (tid < 32) {
        const float* p = gx_base + j0 + tid;
        gc0 = __ldg(p + 0 * H); gc1 = __ldg(p + 1 * H);
        gc2 = __ldg(p + 2 * H); gc3 = __ldg(p + 3 * H);
    }

    for (int step = 0; step < SEQ; step++) {
        // prefetch NEXT step's gx (full-step DRAM-latency cover)
        float gn0 = 0.f, gn1 = 0.f, gn2 = 0.f, gn3 = 0.f;
        if (tid < 32 && step + 1 < SEQ) {
            const float* p = gx_base + (size_t)(step + 1) * G4 + j0 + tid;
            gn0 = __ldg(p + 0 * H); gn1 = __ldg(p + 1 * H);
            gn2 = __ldg(p + 2 * H); gn3 = __ldg(p + 3 * H);
        }

        // ---- wait for all 8 source CTAs to have published h_{step-1} ----
        if (step > 0) {
            unsigned v;
            do {
                asm volatile(
                    "ld.acquire.cluster.shared::cta.u32 %0, [%1];"
                    : "=r"(v) : "r"(fl_local) : "memory");
            } while (__any_sync(~0u, v < (unsigned)step));
        }
        const int rb = step & 1, wb = rb ^ 1;

        // ---- phase 1: partial dot over this thread's 64-wide K slice ----
        const ulonglong2* hv = (const ulonglong2*)&sh_h[rb][s * 64];
        unsigned long long acc0 = 0ull, acc1 = 0ull;
        #pragma unroll
        for (int q = 0; q < 16; q++) {
            ulonglong2 h2 = hv[q];
            asm("fma.rn.f32x2 %0, %1, %2, %0;"
                : "+l"(acc0) : "l"(w2[2 * q]),     "l"(h2.x));
            asm("fma.rn.f32x2 %0, %1, %2, %0;"
                : "+l"(acc1) : "l"(w2[2 * q + 1]), "l"(h2.y));
        }
        float lo0, hi0, lo1, hi1;
        asm("mov.b64 {%0,%1}, %2;" : "=f"(lo0), "=f"(hi0) : "l"(acc0));
        asm("mov.b64 {%0,%1}, %2;" : "=f"(lo1), "=f"(hi1) : "l"(acc1));
        red[g * 4 + s] = (lo0 + hi0) + (lo1 + hi1);   // float4-grouped by g
        __syncthreads();

        // ---- phase 2: warp 0 finishes gates, cell update, broadcast ----
        if (tid < 32) {
            const float4* r4p = (const float4*)red;
            float4 ri = r4p[0 * 32 + tid];
            float4 rf = r4p[1 * 32 + tid];
            float4 rg = r4p[2 * 32 + tid];
            float4 ro = r4p[3 * 32 + tid];
            float gi = gc0 + (ri.x + ri.y) + (ri.z + ri.w);
            float gf = gc1 + (rf.x + rf.y) + (rf.z + rf.w);
            float gg = gc2 + (rg.x + rg.y) + (rg.z + rg.w);
            float go = gc3 + (ro.x + ro.y) + (ro.z + ro.w);

            float ei, ef, eg, eo, iv, fv, gv, ov;
            asm("ex2.approx.f32 %0, %1;" : "=f"(ei) : "f"(-L2E * gi));
            asm("ex2.approx.f32 %0, %1;" : "=f"(ef) : "f"(-L2E * gf));
            asm("ex2.approx.f32 %0, %1;" : "=f"(eg) : "f"(-2.f * L2E * gg));
            asm("ex2.approx.f32 %0, %1;" : "=f"(eo) : "f"(-L2E * go));
            asm("rcp.approx.f32 %0, %1;" : "=f"(iv) : "f"(1.f + ei));
            asm("rcp.approx.f32 %0, %1;" : "=f"(fv) : "f"(1.f + ef));
            asm("rcp.approx.f32 %0, %1;" : "=f"(gv) : "f"(1.f + eg));
            asm("rcp.approx.f32 %0, %1;" : "=f"(ov) : "f"(1.f + eo));
            gv = 2.f * gv - 1.f;                     // tanh(gg)
            cstate = fv * cstate + iv * gv;
            float ec, rc;
            asm("ex2.approx.f32 %0, %1;" : "=f"(ec) : "f"(-2.f * L2E * cstate));
            asm("rcp.approx.f32 %0, %1;" : "=f"(rc) : "f"(1.f + ec));
            float h = ov * (2.f * rc - 1.f);

            #pragma unroll
            for (int cc = 0; cc < 8; cc++) {
                unsigned ad = wb ? raddr1[cc] : raddr0[cc];
                asm volatile("st.shared::cluster.f32 [%0], %1;"
                             :: "r"(ad), "f"(h));
            }
            int pos = dir ? (SEQ - 1 - step) : step;
            g_hs[pos][dir * H + j0 + tid] = h;

            __syncwarp();          // all lanes' h stores happen-before release
            if (tid < 8)
                asm volatile(
                    "st.release.cluster.shared::cluster.u32 [%0], %1;"
                    :: "r"(fl_raddr), "r"((unsigned)(step + 1)) : "memory");

            gc0 = gn0; gc1 = gn1; gc2 = gn2; gc3 = gn3;
        }
    }
    CLUSTER_SYNC_ASM();   // keep peer smem alive until all stores landed
}

// ============================================================================
// Kernel C: emissions em[t][k] = hs[t] . w_lin[k] + b_lin[k]
// also writes eem = exp(em) (unscaled; chunk kernel renorms every step).
// ============================================================================
__global__ void emis_kernel(const float* __restrict__ w_lin,
                            const float* __restrict__ b_lin)
{
    __shared__ float hsm[512];
    __shared__ float redc[512];
    const int t = blockIdx.x, tid = threadIdx.x;
    hsm[tid] = g_hs[t][tid];
    __syncthreads();

    const int k = tid & 31, sl = tid >> 5;
    float p = 0.f;
    #pragma unroll
    for (int m = 0; m < 32; m++)
        p += hsm[sl * 32 + m] * __ldg(&w_lin[k * 512 + sl * 32 + m]);
    redc[sl * 32 + k] = p;
    __syncthreads();

    if (tid < 32) {
        float sum = b_lin[tid];
        #pragma unroll
        for (int s2 = 0; s2 < 16; s2++) sum += redc[s2 * 32 + tid];
        g_em[t][tid] = sum;
        g_eem[t][tid] = exp2f(sum * 1.4426950408889634f);
    }
}

// ============================================================================
// Kernel D1: CRF chunk transfer matrices (PARALLEL over 64 chunks).
// ============================================================================
__global__ void __launch_bounds__(1024, 1)
crf_chunk_kernel(const float* __restrict__ trans)
{
    __shared__ __align__(16) float A[2][NTAGS][36];   // 36: 16B-aligned rows
    __shared__ float s_f;

    const int tid = threadIdx.x;
    const int i = tid >> 5, jj = tid & 31;
    const float L2E = 1.4426950408889634f;

    // column jj of M = exp(trans) in registers
    float Mreg[32];
    #pragma unroll
    for (int k = 0; k < 32; k++)
        Mreg[k] = exp2f(__ldg(&trans[k * NTAGS + jj]) * L2E);

    const int c  = blockIdx.x;
    const int t0 = (c == 0) ? 1 : c * CHUNK;
    const int t1 = (c + 1) * CHUNK;

    A[0][i][jj] = (i == jj) ? 1.f : 0.f;
    float L = 0.f;
    __syncthreads();

    int pb = 0;
    for (int t = t0; t < t1; t++) {
        float eemv = g_eem[t][jj];
        const float4* rowp = (const float4*)&A[pb][i][0];
        float acc = 0.f;
        #pragma unroll
        for (int q = 0; q < 8; q++) {
            float4 r4 = rowp[q];
            acc = fmaf(r4.x, Mreg[4 * q + 0], acc);
            acc = fmaf(r4.y, Mreg[4 * q + 1], acc);
            acc = fmaf(r4.z, Mreg[4 * q + 2], acc);
            acc = fmaf(r4.w, Mreg[4 * q + 3], acc);
        }
        acc *= eemv;
        if (tid == 0) s_f = acc;
        __syncthreads();
        float r;
        asm("rcp.approx.f32 %0, %1;" : "=f"(r) : "f"(s_f));
        A[pb ^ 1][i][jj] = acc * r;
        if (tid == 0) {
            float l2r;
            asm("lg2.approx.f32 %0, %1;" : "=f"(l2r) : "f"(r));
            L -= l2r;
        }
        pb ^= 1;
        __syncthreads();
    }

    g_chunk[c][i][jj] = A[pb][i][jj];
    if (tid == 0) g_chunkL[c] = L;
}

// ============================================================================
// Kernel D2: numerator + sequential combine of 64 chunk matrices + logZ.
// ============================================================================
__global__ void __launch_bounds__(1024, 1)
crf_final_kernel(const float* __restrict__ trans,
                 const float* __restrict__ start_trans,
                 const float* __restrict__ end_trans,
                 const int*   __restrict__ y,
                 float* __restrict__ out)
{
    __shared__ __align__(16) float R[NTAGS][36];
    __shared__ __align__(16) float B[NTAGS][36];
    __shared__ float s_num;
    __shared__ float s_red[32];
    __shared__ float s_f;
    __shared__ float sv0[NTAGS];

    const int tid = threadIdx.x;
    const int lane = tid & 31, warp = tid >> 5;
    const int i = tid >> 5, jj = tid & 31;

    const float L2E = 1.4426950408889634f;
    const float LN2 = 0.6931471805599453f;

    // ---- gold path score (numerator), 1024 threads ----
    float part = 0.f;
    for (int t = tid; t < SEQ; t += 1024) {
        int yt = y[t];
        part += g_em[t][yt];
        if (t > 0) part += trans[y[t - 1] * NTAGS + yt];
    }
    #pragma unroll
    for (int o = 16; o; o >>= 1) part += __shfl_xor_sync(~0u, part, o);
    if (lane == 0) s_red[warp] = part;
    __syncthreads();
    if (tid == 0) {
        float num = start_trans[y[0]] + end_trans[y[SEQ - 1]];
        #pragma unroll
        for (int wv = 0; wv < 32; wv++) num += s_red[wv];
        s_num = num;
    }

    // ---- combine: Rtot = C_0 * C_1 * ... * C_63, renorm each product ----
    R[i][jj] = g_chunk[0][i][jj];
    float L = 0.f;
    if (tid == 0) {
        #pragma unroll
        for (int cc = 0; cc < NCHUNK; cc++) L += g_chunkL[cc];
    }
    __syncthreads();

    for (int c = 1; c < NCHUNK; c++) {
        B[i][jj] = g_chunk[c][i][jj];
        __syncthreads();
        const float4* rowp = (const float4*)&R[i][0];
        float acc = 0.f;
        #pragma unroll
        for (int q = 0; q < 8; q++) {
            float4 r4 = rowp[q];
            acc = fmaf(r4.x, B[4 * q + 0][jj], acc);
            acc = fmaf(r4.y, B[4 * q + 1][jj], acc);
            acc = fmaf(r4.z, B[4 * q + 2][jj], acc);
            acc = fmaf(r4.w, B[4 * q + 3][jj], acc);
        }
        if (tid == 0) s_f = acc;
        __syncthreads();
        float r;
        asm("rcp.approx.f32 %0, %1;" : "=f"(r) : "f"(s_f));
        R[i][jj] = acc * r;
        if (tid == 0) {
            float l2r;
            asm("lg2.approx.f32 %0, %1;" : "=f"(l2r) : "f"(r));
            L -= l2r;
        }
        __syncthreads();
    }

    // ---- alpha0 fold-in + end, warp 0 ----
    if (warp == 0) {
        sv0[lane] = exp2f((start_trans[lane] + g_em[0][lane]) * L2E);
        __syncwarp();
        float acc = 0.f;
        #pragma unroll
        for (int k = 0; k < 32; k++)
            acc = fmaf(sv0[k], R[k][lane], acc);
        float term = acc * exp2f(end_trans[lane] * L2E);
        #pragma unroll
        for (int o = 16; o; o >>= 1) term += __shfl_xor_sync(~0u, term, o);
        if (lane == 0) {
            float l2S;
            asm("lg2.approx.f32 %0, %1;" : "=f"(l2S) : "f"(term));
            out[0] = (l2S + L) * LN2 - s_num;
        }
    }
}

// ============================================================================
extern "C" void kernel_launch(void* const* d_in, const int* in_sizes, int n_in,
                              void* d_out, int out_size)
{
    const float* embed       = (const float*)d_in[0];
    const float* w_ih_f      = (const float*)d_in[1];
    const float* w_hh_f      = (const float*)d_in[2];
    const float* b_ih_f      = (const float*)d_in[3];
    const float* b_hh_f      = (const float*)d_in[4];
    const float* w_ih_b      = (const float*)d_in[5];
    const float* w_hh_b      = (const float*)d_in[6];
    const float* b_ih_b      = (const float*)d_in[7];
    const float* b_hh_b      = (const float*)d_in[8];
    const float* w_lin       = (const float*)d_in[9];
    const float* b_lin       = (const float*)d_in[10];
    const float* trans       = (const float*)d_in[11];
    const float* start_trans = (const float*)d_in[12];
    const float* end_trans   = (const float*)d_in[13];
    const int*   x           = (const int*)d_in[14];
    const int*   y           = (const int*)d_in[15];

    dim3 gA(SEQ / 64, G4 / 64, 2);
    gx_kernel<<<gA, 256>>>(embed, w_ih_f, b_ih_f, b_hh_f,
                           w_ih_b, b_ih_b, b_hh_b, x);
    lstm_kernel<<<16, 512>>>(w_hh_f, w_hh_b);
    emis_kernel<<<SEQ, 512>>>(w_lin, b_lin);
    crf_chunk_kernel<<<NCHUNK, 1024>>>(trans);
    crf_final_kernel<<<1, 1024>>>(trans, start_trans, end_trans, y,
                                  (float*)d_out);
}

// round 15
// speedup vs baseline: 1.0176x; 1.0176x over previous
#include <cuda_runtime.h>
#include <cstdint>
#include <math.h>

#define SEQ   4096
#define EMB   256
#define H     256
#define G4    1024   // 4*H
#define NTAGS 32
#define NCHUNK 64
#define CHUNK  64

// ---------------- scratch (device globals: no allocation allowed) ----------
__device__ float g_gx[2][SEQ][G4];       // input projections per direction
__device__ float g_hs[SEQ][2 * H];       // concatenated BiLSTM hidden states
__device__ float g_em[SEQ][NTAGS];       // emissions (log space)
__device__ float g_eem[SEQ][NTAGS];      // exp(em)  (linear space, UNSCALED)
__device__ float g_chunk[NCHUNK][NTAGS][NTAGS];  // chunk transfer matrices
__device__ float g_chunkL[NCHUNK];               // their log2 scale factors

__device__ __forceinline__ unsigned smem_u32(const void* p) {
    return (unsigned)__cvta_generic_to_shared(p);
}

#define CLUSTER_ARRIVE() \
    asm volatile("barrier.cluster.arrive.aligned;" ::: "memory")
#define CLUSTER_WAIT() \
    asm volatile("barrier.cluster.wait.aligned;"   ::: "memory")
#define CLUSTER_SYNC_ASM() do { CLUSTER_ARRIVE(); CLUSTER_WAIT(); } while (0)

// ============================================================================
// Kernel A: gx[d][t][r] = emb_d[t] . w_ih_d[r] + b_ih[r] + b_hh[r]
// 128(t) x 64(r) tiles, BK=32, 8x4 per thread (32 FMA per 12 LDS).
// ============================================================================
__global__ void __launch_bounds__(256, 1)
gx_kernel(const float* __restrict__ embed,
          const float* __restrict__ w_ih_f,
          const float* __restrict__ b_ih_f,
          const float* __restrict__ b_hh_f,
          const float* __restrict__ w_ih_b,
          const float* __restrict__ b_ih_b,
          const float* __restrict__ b_hh_b,
          const int*   __restrict__ x)
{
    const int dir = blockIdx.z;
    const float* w_ih = dir ? w_ih_b : w_ih_f;
    const float* b_ih = dir ? b_ih_b : b_ih_f;
    const float* b_hh = dir ? b_hh_b : b_hh_f;

    __shared__ float As[128][33];
    __shared__ float Bs[64][33];
    __shared__ int   toks[128];

    const int tid = threadIdx.x;
    const int t0 = blockIdx.x * 128;
    const int r0 = blockIdx.y * 64;

    if (tid < 128) {
        int t = t0 + tid;
        int p = dir ? (SEQ - 1 - t) : t;
        toks[tid] = x[p];
    }
    __syncthreads();

    const int tx = tid & 15, ty = tid >> 4;
    float c[8][4] = {};

    for (int k0 = 0; k0 < EMB; k0 += 32) {
        #pragma unroll
        for (int i = tid; i < 128 * 32; i += 256) {
            int row = i >> 5, k = i & 31;
            As[row][k] = embed[(size_t)toks[row] * EMB + k0 + k];
        }
        #pragma unroll
        for (int i = tid; i < 64 * 32; i += 256) {
            int row = i >> 5, k = i & 31;
            Bs[row][k] = w_ih[(size_t)(r0 + row) * EMB + k0 + k];
        }
        __syncthreads();
        #pragma unroll
        for (int kk = 0; kk < 32; kk++) {
            float a[8], b[4];
            #pragma unroll
            for (int u = 0; u < 8; u++) a[u] = As[ty * 8 + u][kk];
            #pragma unroll
            for (int v = 0; v < 4; v++) b[v] = Bs[tx * 4 + v][kk];
            #pragma unroll
            for (int u = 0; u < 8; u++)
                #pragma unroll
                for (int v = 0; v < 4; v++)
                    c[u][v] += a[u] * b[v];
        }
        __syncthreads();
    }

    #pragma unroll
    for (int u = 0; u < 8; u++) {
        int t = t0 + ty * 8 + u;
        #pragma unroll
        for (int v = 0; v < 4; v++) {
            int r = r0 + tx * 4 + v;
            g_gx[dir][t][r] = c[u][v] + b_ih[r] + b_hh[r];
        }
    }
}

// ============================================================================
// Kernel B: sequential BiLSTM recurrence (2 clusters of 8 CTAs).
// Best-known configuration (r8 compute + r12 CRF era):
//   * warp-uniform K slice, smem reduction red[s*128+g] (stride-1 STS,
//     conflict-free — the r12 float4 regrouping caused 8-way conflicts),
//   * f32x2 FFMA matvec, weights in registers,
//   * warp-0 tail with ex2/rcp activations, register raddr double buffer,
//   * HW cluster barrier, split arrive/wait (all software syncs measured
//     slower: r5/r10 mbarrier atomics, r14 acquire-load polling),
//   * gx prefetched one full step ahead.
// ============================================================================
__global__ void __cluster_dims__(8, 1, 1) __launch_bounds__(512, 1)
lstm_kernel(const float* __restrict__ w_hh_f, const float* __restrict__ w_hh_b)
{
    __shared__ __align__(16) float sh_h[2][256];   // double-buffered h
    __shared__ float red[512];

    const int tid = threadIdx.x;
    const int dir = blockIdx.x >> 3;
    unsigned rank;
    asm("mov.u32 %0, %%cluster_ctarank;" : "=r"(rank));
    const int j0 = (int)rank * 32;

    const float* __restrict__ w_hh = dir ? w_hh_b : w_hh_f;

    const int g    = ((tid >> 7) << 5) | (tid & 31);  // 0..127 local gate id
    const int s    = (tid >> 5) & 3;                  // 0..3  K slice
    const int gate = g >> 5;                          // i,f,g,o
    const int j    = g & 31;                          // hidden index within CTA
    const int row  = gate * H + j0 + j;               // global gate row

    // ---- weights into registers as packed f32x2 pairs ----
    unsigned long long w2[32];
    {
        const ulonglong2* wv =
            (const ulonglong2*)(w_hh + (size_t)row * H + s * 64);
        #pragma unroll
        for (int q = 0; q < 16; q++) {
            ulonglong2 v = wv[q];
            w2[2 * q] = v.x; w2[2 * q + 1] = v.y;
        }
    }

    if (tid < 256) { sh_h[0][tid] = 0.f; sh_h[1][tid] = 0.f; }

    // remote h addresses in two separate register arrays (no LDL)
    unsigned raddr0[8], raddr1[8];
    if (tid < 32) {
        unsigned la0 = smem_u32(&sh_h[0][j0 + tid]);
        unsigned la1 = smem_u32(&sh_h[1][j0 + tid]);
        #pragma unroll
        for (int cc = 0; cc < 8; cc++) {
            asm("mapa.shared::cluster.u32 %0, %1, %2;"
                : "=r"(raddr0[cc]) : "r"(la0), "r"(cc));
            asm("mapa.shared::cluster.u32 %0, %1, %2;"
                : "=r"(raddr1[cc]) : "r"(la1), "r"(cc));
        }
    }

    CLUSTER_SYNC_ASM();   // zeros visible cluster-wide

    float cstate = 0.f;
    const float* __restrict__ gx_base = &g_gx[dir][0][0];
    const float L2E = 1.4426950408889634f;

    // preload gx for step 0
    float gc0 = 0.f, gc1 = 0.f, gc2 = 0.f, gc3 = 0.f;
    if (tid < 32) {
        const float* p = gx_base + j0 + tid;
        gc0 = __ldg(p + 0 * H); gc1 = __ldg(p + 1 * H);
        gc2 = __ldg(p + 2 * H); gc3 = __ldg(p + 3 * H);
    }

    for (int step = 0; step < SEQ; step++) {
        // prefetch NEXT step's gx (full-step DRAM-latency cover)
        float gn0 = 0.f, gn1 = 0.f, gn2 = 0.f, gn3 = 0.f;
        if (tid < 32 && step + 1 < SEQ) {
            const float* p = gx_base + (size_t)(step + 1) * G4 + j0 + tid;
            gn0 = __ldg(p + 0 * H); gn1 = __ldg(p + 1 * H);
            gn2 = __ldg(p + 2 * H); gn3 = __ldg(p + 3 * H);
        }

        if (step > 0) CLUSTER_WAIT();   // h_{t-1} remote stores published
        const int rb = step & 1, wb = rb ^ 1;

        // ---- phase 1: partial dot over this thread's 64-wide K slice ----
        const ulonglong2* hv = (const ulonglong2*)&sh_h[rb][s * 64];
        unsigned long long acc0 = 0ull, acc1 = 0ull;
        #pragma unroll
        for (int q = 0; q < 16; q++) {
            ulonglong2 h2 = hv[q];
            asm("fma.rn.f32x2 %0, %1, %2, %0;"
                : "+l"(acc0) : "l"(w2[2 * q]),     "l"(h2.x));
            asm("fma.rn.f32x2 %0, %1, %2, %0;"
                : "+l"(acc1) : "l"(w2[2 * q + 1]), "l"(h2.y));
        }
        float lo0, hi0, lo1, hi1;
        asm("mov.b64 {%0,%1}, %2;" : "=f"(lo0), "=f"(hi0) : "l"(acc0));
        asm("mov.b64 {%0,%1}, %2;" : "=f"(lo1), "=f"(hi1) : "l"(acc1));
        red[s * 128 + g] = (lo0 + hi0) + (lo1 + hi1);   // stride-1: no conflicts
        __syncthreads();

        // ---- phase 2: warp 0 finishes gates, cell update, broadcast ----
        if (tid < 32) {
            float gi = gc0, gf = gc1, gg = gc2, go = gc3;
            #pragma unroll
            for (int sl = 0; sl < 4; sl++) {
                gi += red[sl * 128 + 0 * 32 + tid];
                gf += red[sl * 128 + 1 * 32 + tid];
                gg += red[sl * 128 + 2 * 32 + tid];
                go += red[sl * 128 + 3 * 32 + tid];
            }
            float ei, ef, eg, eo, iv, fv, gv, ov;
            asm("ex2.approx.f32 %0, %1;" : "=f"(ei) : "f"(-L2E * gi));
            asm("ex2.approx.f32 %0, %1;" : "=f"(ef) : "f"(-L2E * gf));
            asm("ex2.approx.f32 %0, %1;" : "=f"(eg) : "f"(-2.f * L2E * gg));
            asm("ex2.approx.f32 %0, %1;" : "=f"(eo) : "f"(-L2E * go));
            asm("rcp.approx.f32 %0, %1;" : "=f"(iv) : "f"(1.f + ei));
            asm("rcp.approx.f32 %0, %1;" : "=f"(fv) : "f"(1.f + ef));
            asm("rcp.approx.f32 %0, %1;" : "=f"(gv) : "f"(1.f + eg));
            asm("rcp.approx.f32 %0, %1;" : "=f"(ov) : "f"(1.f + eo));
            gv = 2.f * gv - 1.f;                     // tanh(gg)
            cstate = fv * cstate + iv * gv;
            float ec, rc;
            asm("ex2.approx.f32 %0, %1;" : "=f"(ec) : "f"(-2.f * L2E * cstate));
            asm("rcp.approx.f32 %0, %1;" : "=f"(rc) : "f"(1.f + ec));
            float h = ov * (2.f * rc - 1.f);

            #pragma unroll
            for (int cc = 0; cc < 8; cc++) {
                unsigned ad = wb ? raddr1[cc] : raddr0[cc];
                asm volatile("st.shared::cluster.f32 [%0], %1;"
                             :: "r"(ad), "f"(h));
            }
            int pos = dir ? (SEQ - 1 - step) : step;
            g_hs[pos][dir * H + j0 + tid] = h;

            gc0 = gn0; gc1 = gn1; gc2 = gn2; gc3 = gn3;
        }
        CLUSTER_ARRIVE();   // release: publishes this step's remote h stores
    }
    CLUSTER_WAIT();         // match final arrives; smem alive until all landed
}

// ============================================================================
// Kernel C: emissions em[t][k] = hs[t] . w_lin[k] + b_lin[k]
// also writes eem = exp(em) (unscaled; chunk kernel renorms every step).
// ============================================================================
__global__ void emis_kernel(const float* __restrict__ w_lin,
                            const float* __restrict__ b_lin)
{
    __shared__ float hsm[512];
    __shared__ float redc[512];
    const int t = blockIdx.x, tid = threadIdx.x;
    hsm[tid] = g_hs[t][tid];
    __syncthreads();

    const int k = tid & 31, sl = tid >> 5;
    float p = 0.f;
    #pragma unroll
    for (int m = 0; m < 32; m++)
        p += hsm[sl * 32 + m] * __ldg(&w_lin[k * 512 + sl * 32 + m]);
    redc[sl * 32 + k] = p;
    __syncthreads();

    if (tid < 32) {
        float sum = b_lin[tid];
        #pragma unroll
        for (int s2 = 0; s2 < 16; s2++) sum += redc[s2 * 32 + tid];
        g_em[t][tid] = sum;
        g_eem[t][tid] = exp2f(sum * 1.4426950408889634f);
    }
}

// ============================================================================
// Kernel D1: CRF chunk transfer matrices (PARALLEL over 64 chunks).
// ============================================================================
__global__ void __launch_bounds__(1024, 1)
crf_chunk_kernel(const float* __restrict__ trans)
{
    __shared__ __align__(16) float A[2][NTAGS][36];   // 36: 16B-aligned rows
    __shared__ float s_f;

    const int tid = threadIdx.x;
    const int i = tid >> 5, jj = tid & 31;
    const float L2E = 1.4426950408889634f;

    // column jj of M = exp(trans) in registers
    float Mreg[32];
    #pragma unroll
    for (int k = 0; k < 32; k++)
        Mreg[k] = exp2f(__ldg(&trans[k * NTAGS + jj]) * L2E);

    const int c  = blockIdx.x;
    const int t0 = (c == 0) ? 1 : c * CHUNK;
    const int t1 = (c + 1) * CHUNK;

    A[0][i][jj] = (i == jj) ? 1.f : 0.f;
    float L = 0.f;
    __syncthreads();

    int pb = 0;
    for (int t = t0; t < t1; t++) {
        float eemv = g_eem[t][jj];
        const float4* rowp = (const float4*)&A[pb][i][0];
        float acc = 0.f;
        #pragma unroll
        for (int q = 0; q < 8; q++) {
            float4 r4 = rowp[q];
            acc = fmaf(r4.x, Mreg[4 * q + 0], acc);
            acc = fmaf(r4.y, Mreg[4 * q + 1], acc);
            acc = fmaf(r4.z, Mreg[4 * q + 2], acc);
            acc = fmaf(r4.w, Mreg[4 * q + 3], acc);
        }
        acc *= eemv;
        if (tid == 0) s_f = acc;
        __syncthreads();
        float r;
        asm("rcp.approx.f32 %0, %1;" : "=f"(r) : "f"(s_f));
        A[pb ^ 1][i][jj] = acc * r;
        if (tid == 0) {
            float l2r;
            asm("lg2.approx.f32 %0, %1;" : "=f"(l2r) : "f"(r));
            L -= l2r;
        }
        pb ^= 1;
        __syncthreads();
    }

    g_chunk[c][i][jj] = A[pb][i][jj];
    if (tid == 0) g_chunkL[c] = L;
}

// ============================================================================
// Kernel D2: numerator + sequential combine of 64 chunk matrices + logZ.
// ============================================================================
__global__ void __launch_bounds__(1024, 1)
crf_final_kernel(const float* __restrict__ trans,
                 const float* __restrict__ start_trans,
                 const float* __restrict__ end_trans,
                 const int*   __restrict__ y,
                 float* __restrict__ out)
{
    __shared__ __align__(16) float R[NTAGS][36];
    __shared__ __align__(16) float B[NTAGS][36];
    __shared__ float s_num;
    __shared__ float s_red[32];
    __shared__ float s_f;
    __shared__ float sv0[NTAGS];

    const int tid = threadIdx.x;
    const int lane = tid & 31, warp = tid >> 5;
    const int i = tid >> 5, jj = tid & 31;

    const float L2E = 1.4426950408889634f;
    const float LN2 = 0.6931471805599453f;

    // ---- gold path score (numerator), 1024 threads ----
    float part = 0.f;
    for (int t = tid; t < SEQ; t += 1024) {
        int yt = y[t];
        part += g_em[t][yt];
        if (t > 0) part += trans[y[t - 1] * NTAGS + yt];
    }
    #pragma unroll
    for (int o = 16; o; o >>= 1) part += __shfl_xor_sync(~0u, part, o);
    if (lane == 0) s_red[warp] = part;
    __syncthreads();
    if (tid == 0) {
        float num = start_trans[y[0]] + end_trans[y[SEQ - 1]];
        #pragma unroll
        for (int wv = 0; wv < 32; wv++) num += s_red[wv];
        s_num = num;
    }

    // ---- combine: Rtot = C_0 * C_1 * ... * C_63, renorm each product ----
    R[i][jj] = g_chunk[0][i][jj];
    float L = 0.f;
    if (tid == 0) {
        #pragma unroll
        for (int cc = 0; cc < NCHUNK; cc++) L += g_chunkL[cc];
    }
    __syncthreads();

    for (int c = 1; c < NCHUNK; c++) {
        B[i][jj] = g_chunk[c][i][jj];
        __syncthreads();
        const float4* rowp = (const float4*)&R[i][0];
        float acc = 0.f;
        #pragma unroll
        for (int q = 0; q < 8; q++) {
            float4 r4 = rowp[q];
            acc = fmaf(r4.x, B[4 * q + 0][jj], acc);
            acc = fmaf(r4.y, B[4 * q + 1][jj], acc);
            acc = fmaf(r4.z, B[4 * q + 2][jj], acc);
            acc = fmaf(r4.w, B[4 * q + 3][jj], acc);
        }
        if (tid == 0) s_f = acc;
        __syncthreads();
        float r;
        asm("rcp.approx.f32 %0, %1;" : "=f"(r) : "f"(s_f));
        R[i][jj] = acc * r;
        if (tid == 0) {
            float l2r;
            asm("lg2.approx.f32 %0, %1;" : "=f"(l2r) : "f"(r));
            L -= l2r;
        }
        __syncthreads();
    }

    // ---- alpha0 fold-in + end, warp 0 ----
    if (warp == 0) {
        sv0[lane] = exp2f((start_trans[lane] + g_em[0][lane]) * L2E);
        __syncwarp();
        float acc = 0.f;
        #pragma unroll
        for (int k = 0; k < 32; k++)
            acc = fmaf(sv0[k], R[k][lane], acc);
        float term = acc * exp2f(end_trans[lane] * L2E);
        #pragma unroll
        for (int o = 16; o; o >>= 1) term += __shfl_xor_sync(~0u, term, o);
        if (lane == 0) {
            float l2S;
            asm("lg2.approx.f32 %0, %1;" : "=f"(l2S) : "f"(term));
            out[0] = (l2S + L) * LN2 - s_num;
        }
    }
}

// ============================================================================
extern "C" void kernel_launch(void* const* d_in, const int* in_sizes, int n_in,
                              void* d_out, int out_size)
{
    const float* embed       = (const float*)d_in[0];
    const float* w_ih_f      = (const float*)d_in[1];
    const float* w_hh_f      = (const float*)d_in[2];
    const float* b_ih_f      = (const float*)d_in[3];
    const float* b_hh_f      = (const float*)d_in[4];
    const float* w_ih_b      = (const float*)d_in[5];
    const float* w_hh_b      = (const float*)d_in[6];
    const float* b_ih_b      = (const float*)d_in[7];
    const float* b_hh_b      = (const float*)d_in[8];
    const float* w_lin       = (const float*)d_in[9];
    const float* b_lin       = (const float*)d_in[10];
    const float* trans       = (const float*)d_in[11];
    const float* start_trans = (const float*)d_in[12];
    const float* end_trans   = (const float*)d_in[13];
    const int*   x           = (const int*)d_in[14];
    const int*   y           = (const int*)d_in[15];

    dim3 gA(SEQ / 128, G4 / 64, 2);
    gx_kernel<<<gA, 256>>>(embed, w_ih_f, b_ih_f, b_hh_f,
                           w_ih_b, b_ih_b, b_hh_b, x);
    lstm_kernel<<<16, 512>>>(w_hh_f, w_hh_b);
    emis_kernel<<<SEQ, 512>>>(w_lin, b_lin);
    crf_chunk_kernel<<<NCHUNK, 1024>>>(trans);
    crf_final_kernel<<<1, 1024>>>(trans, start_trans, end_trans, y,
                                  (float*)d_out);
}

// round 16
// speedup vs baseline: 1.0330x; 1.0151x over previous
#include <cuda_runtime.h>
#include <cstdint>
#include <math.h>

#define SEQ   4096
#define EMB   256
#define H     256
#define G4    1024   // 4*H
#define NTAGS 32
#define NCHUNK 64
#define CHUNK  64

// ---------------- scratch (device globals: no allocation allowed) ----------
__device__ float g_gx[2][SEQ][G4];       // input projections per direction
__device__ float g_hs[SEQ][2 * H];       // concatenated BiLSTM hidden states
__device__ float g_em[SEQ][NTAGS];       // emissions (log space)
__device__ float g_eem[SEQ][NTAGS];      // exp(em)  (linear space, UNSCALED)
__device__ float g_chunk[NCHUNK][NTAGS][NTAGS];  // chunk transfer matrices
__device__ float g_chunkL[NCHUNK];               // their log2 scale factors

__device__ __forceinline__ unsigned smem_u32(const void* p) {
    return (unsigned)__cvta_generic_to_shared(p);
}

#define CLUSTER_ARRIVE() \
    asm volatile("barrier.cluster.arrive.aligned;" ::: "memory")
#define CLUSTER_WAIT() \
    asm volatile("barrier.cluster.wait.aligned;"   ::: "memory")
#define CLUSTER_SYNC_ASM() do { CLUSTER_ARRIVE(); CLUSTER_WAIT(); } while (0)

#define FFMA2(acc, a, b) \
    asm("fma.rn.f32x2 %0, %1, %2, %0;" : "+l"(acc) : "l"(a), "l"(b))

// ============================================================================
// Kernel A: gx[d][t][r] = emb_d[t] . w_ih_d[r] + b_ih[r] + b_hh[r]
// 64x64 tiles, BK=32, f32x2 inner product (K-paired accumulators).
// smem as ull[64][17]: slot = 17*row + k2, slot%16 = (row+k2)%16 ->
// LDS.64 conflict-free for both the A row-broadcast and the B 16-lane
// column reads (rows interleaved: thread covers rows {idx+16*u}).
// ============================================================================
__global__ void __launch_bounds__(256, 1)
gx_kernel(const float* __restrict__ embed,
          const float* __restrict__ w_ih_f,
          const float* __restrict__ b_ih_f,
          const float* __restrict__ b_hh_f,
          const float* __restrict__ w_ih_b,
          const float* __restrict__ b_ih_b,
          const float* __restrict__ b_hh_b,
          const int*   __restrict__ x)
{
    const int dir = blockIdx.z;
    const float* w_ih = dir ? w_ih_b : w_ih_f;
    const float* b_ih = dir ? b_ih_b : b_ih_f;
    const float* b_hh = dir ? b_hh_b : b_hh_f;

    __shared__ unsigned long long As2[64][17];
    __shared__ unsigned long long Bs2[64][17];
    __shared__ int toks[64];

    const int tid = threadIdx.x;
    const int t0 = blockIdx.x * 64;
    const int r0 = blockIdx.y * 64;

    if (tid < 64) {
        int t = t0 + tid;
        int p = dir ? (SEQ - 1 - t) : t;
        toks[tid] = x[p];
    }
    __syncthreads();

    const int tx = tid & 15, ty = tid >> 4;
    unsigned long long c2[4][4];
    #pragma unroll
    for (int u = 0; u < 4; u++)
        #pragma unroll
        for (int v = 0; v < 4; v++) c2[u][v] = 0ull;

    for (int k0 = 0; k0 < EMB; k0 += 32) {
        #pragma unroll
        for (int i = tid; i < 64 * 16; i += 256) {
            int row = i >> 4, k2 = i & 15;
            As2[row][k2] = *(const unsigned long long*)
                &embed[(size_t)toks[row] * EMB + k0 + 2 * k2];
        }
        #pragma unroll
        for (int i = tid; i < 64 * 16; i += 256) {
            int row = i >> 4, k2 = i & 15;
            Bs2[row][k2] = *(const unsigned long long*)
                &w_ih[(size_t)(r0 + row) * EMB + k0 + 2 * k2];
        }
        __syncthreads();
        #pragma unroll
        for (int k2 = 0; k2 < 16; k2++) {
            unsigned long long a2[4], b2[4];
            #pragma unroll
            for (int u = 0; u < 4; u++) a2[u] = As2[ty + 16 * u][k2];
            #pragma unroll
            for (int v = 0; v < 4; v++) b2[v] = Bs2[tx + 16 * v][k2];
            #pragma unroll
            for (int u = 0; u < 4; u++)
                #pragma unroll
                for (int v = 0; v < 4; v++)
                    FFMA2(c2[u][v], a2[u], b2[v]);
        }
        __syncthreads();
    }

    #pragma unroll
    for (int u = 0; u < 4; u++) {
        int t = t0 + ty + 16 * u;
        #pragma unroll
        for (int v = 0; v < 4; v++) {
            int r = r0 + tx + 16 * v;
            float lo, hi;
            asm("mov.b64 {%0,%1}, %2;" : "=f"(lo), "=f"(hi) : "l"(c2[u][v]));
            g_gx[dir][t][r] = (lo + hi) + b_ih[r] + b_hh[r];
        }
    }
}

// ============================================================================
// Kernel B: sequential BiLSTM recurrence (2 clusters of 8 CTAs).
// r12 proven config (HW cluster barrier split arrive/wait, red[s*128+g],
// f32x2 matvec, register raddr, one-step-ahead gx prefetch) with ONE delta:
// the phase-2 tail is spread over 4 warps (warps 0-3 = the 4 SMSPs, 8
// hidden-unit owners per warp) so its MUFU/LDS/remote-ST serialization
// quarters instead of bottlenecking one warp.
// ============================================================================
__global__ void __cluster_dims__(8, 1, 1) __launch_bounds__(512, 1)
lstm_kernel(const float* __restrict__ w_hh_f, const float* __restrict__ w_hh_b)
{
    __shared__ __align__(16) float sh_h[2][256];   // double-buffered h
    __shared__ float red[512];

    const int tid = threadIdx.x;
    const int dir = blockIdx.x >> 3;
    unsigned rank;
    asm("mov.u32 %0, %%cluster_ctarank;" : "=r"(rank));
    const int j0 = (int)rank * 32;

    const float* __restrict__ w_hh = dir ? w_hh_b : w_hh_f;

    const int g    = ((tid >> 7) << 5) | (tid & 31);  // 0..127 local gate id
    const int s    = (tid >> 5) & 3;                  // 0..3  K slice
    const int gate = g >> 5;                          // i,f,g,o
    const int j    = g & 31;                          // hidden index within CTA
    const int row  = gate * H + j0 + j;               // global gate row

    // owners: warps 0-3, lanes 0-7 -> 32 owner threads on 4 distinct SMSPs
    const bool owner = (tid < 128) && ((tid & 31) < 8);
    const int  oj    = ((tid >> 5) << 3) | (tid & 7); // owned hidden 0..31
    const int  orow  = j0 + oj;                       // gate-row base (gate 0)

    // ---- weights into registers as packed f32x2 pairs ----
    unsigned long long w2[32];
    {
        const ulonglong2* wv =
            (const ulonglong2*)(w_hh + (size_t)row * H + s * 64);
        #pragma unroll
        for (int q = 0; q < 16; q++) {
            ulonglong2 v = wv[q];
            w2[2 * q] = v.x; w2[2 * q + 1] = v.y;
        }
    }

    if (tid < 256) { sh_h[0][tid] = 0.f; sh_h[1][tid] = 0.f; }

    // remote h addresses in two separate register arrays (no LDL)
    unsigned raddr0[8], raddr1[8];
    if (owner) {
        unsigned la0 = smem_u32(&sh_h[0][orow]);
        unsigned la1 = smem_u32(&sh_h[1][orow]);
        #pragma unroll
        for (int cc = 0; cc < 8; cc++) {
            asm("mapa.shared::cluster.u32 %0, %1, %2;"
                : "=r"(raddr0[cc]) : "r"(la0), "r"(cc));
            asm("mapa.shared::cluster.u32 %0, %1, %2;"
                : "=r"(raddr1[cc]) : "r"(la1), "r"(cc));
        }
    }

    CLUSTER_SYNC_ASM();   // zeros visible cluster-wide

    float cstate = 0.f;
    const float* __restrict__ gx_base = &g_gx[dir][0][0];
    const float L2E = 1.4426950408889634f;

    // preload gx for step 0
    float gc0 = 0.f, gc1 = 0.f, gc2 = 0.f, gc3 = 0.f;
    if (owner) {
        const float* p = gx_base + orow;
        gc0 = __ldg(p + 0 * H); gc1 = __ldg(p + 1 * H);
        gc2 = __ldg(p + 2 * H); gc3 = __ldg(p + 3 * H);
    }

    for (int step = 0; step < SEQ; step++) {
        // prefetch NEXT step's gx (full-step DRAM-latency cover)
        float gn0 = 0.f, gn1 = 0.f, gn2 = 0.f, gn3 = 0.f;
        if (owner && step + 1 < SEQ) {
            const float* p = gx_base + (size_t)(step + 1) * G4 + orow;
            gn0 = __ldg(p + 0 * H); gn1 = __ldg(p + 1 * H);
            gn2 = __ldg(p + 2 * H); gn3 = __ldg(p + 3 * H);
        }

        if (step > 0) CLUSTER_WAIT();   // h_{t-1} remote stores published
        const int rb = step & 1, wb = rb ^ 1;

        // ---- phase 1: partial dot over this thread's 64-wide K slice ----
        const ulonglong2* hv = (const ulonglong2*)&sh_h[rb][s * 64];
        unsigned long long acc0 = 0ull, acc1 = 0ull;
        #pragma unroll
        for (int q = 0; q < 16; q++) {
            ulonglong2 h2 = hv[q];
            FFMA2(acc0, w2[2 * q],     h2.x);
            FFMA2(acc1, w2[2 * q + 1], h2.y);
        }
        float lo0, hi0, lo1, hi1;
        asm("mov.b64 {%0,%1}, %2;" : "=f"(lo0), "=f"(hi0) : "l"(acc0));
        asm("mov.b64 {%0,%1}, %2;" : "=f"(lo1), "=f"(hi1) : "l"(acc1));
        red[s * 128 + g] = (lo0 + hi0) + (lo1 + hi1);   // stride-1: no conflicts
        __syncthreads();

        // ---- phase 2: 4 owner warps finish gates, cell update, bcast ----
        if (owner) {
            float gi = gc0, gf = gc1, gg = gc2, go = gc3;
            #pragma unroll
            for (int sl = 0; sl < 4; sl++) {
                gi += red[sl * 128 + 0 * 32 + oj];
                gf += red[sl * 128 + 1 * 32 + oj];
                gg += red[sl * 128 + 2 * 32 + oj];
                go += red[sl * 128 + 3 * 32 + oj];
            }
            float ei, ef, eg, eo, iv, fv, gv, ov;
            asm("ex2.approx.f32 %0, %1;" : "=f"(ei) : "f"(-L2E * gi));
            asm("ex2.approx.f32 %0, %1;" : "=f"(ef) : "f"(-L2E * gf));
            asm("ex2.approx.f32 %0, %1;" : "=f"(eg) : "f"(-2.f * L2E * gg));
            asm("ex2.approx.f32 %0, %1;" : "=f"(eo) : "f"(-L2E * go));
            asm("rcp.approx.f32 %0, %1;" : "=f"(iv) : "f"(1.f + ei));
            asm("rcp.approx.f32 %0, %1;" : "=f"(fv) : "f"(1.f + ef));
            asm("rcp.approx.f32 %0, %1;" : "=f"(gv) : "f"(1.f + eg));
            asm("rcp.approx.f32 %0, %1;" : "=f"(ov) : "f"(1.f + eo));
            gv = 2.f * gv - 1.f;                     // tanh(gg)
            cstate = fv * cstate + iv * gv;
            float ec, rc;
            asm("ex2.approx.f32 %0, %1;" : "=f"(ec) : "f"(-2.f * L2E * cstate));
            asm("rcp.approx.f32 %0, %1;" : "=f"(rc) : "f"(1.f + ec));
            float h = ov * (2.f * rc - 1.f);

            #pragma unroll
            for (int cc = 0; cc < 8; cc++) {
                unsigned ad = wb ? raddr1[cc] : raddr0[cc];
                asm volatile("st.shared::cluster.f32 [%0], %1;"
                             :: "r"(ad), "f"(h));
            }
            int pos = dir ? (SEQ - 1 - step) : step;
            g_hs[pos][dir * H + orow] = h;

            gc0 = gn0; gc1 = gn1; gc2 = gn2; gc3 = gn3;
        }
        CLUSTER_ARRIVE();   // release: each thread's arrive publishes its stores
    }
    CLUSTER_WAIT();         // match final arrives; smem alive until all landed
}

// ============================================================================
// Kernel C: emissions em[t][k] = hs[t] . w_lin[k] + b_lin[k]
// also writes eem = exp(em) (unscaled; chunk kernel renorms every step).
// ============================================================================
__global__ void emis_kernel(const float* __restrict__ w_lin,
                            const float* __restrict__ b_lin)
{
    __shared__ float hsm[512];
    __shared__ float redc[512];
    const int t = blockIdx.x, tid = threadIdx.x;
    hsm[tid] = g_hs[t][tid];
    __syncthreads();

    const int k = tid & 31, sl = tid >> 5;
    float p = 0.f;
    #pragma unroll
    for (int m = 0; m < 32; m++)
        p += hsm[sl * 32 + m] * __ldg(&w_lin[k * 512 + sl * 32 + m]);
    redc[sl * 32 + k] = p;
    __syncthreads();

    if (tid < 32) {
        float sum = b_lin[tid];
        #pragma unroll
        for (int s2 = 0; s2 < 16; s2++) sum += redc[s2 * 32 + tid];
        g_em[t][tid] = sum;
        g_eem[t][tid] = exp2f(sum * 1.4426950408889634f);
    }
}

// ============================================================================
// Kernel D1: CRF chunk transfer matrices (PARALLEL over 64 chunks).
// ============================================================================
__global__ void __launch_bounds__(1024, 1)
crf_chunk_kernel(const float* __restrict__ trans)
{
    __shared__ __align__(16) float A[2][NTAGS][36];   // 36: 16B-aligned rows
    __shared__ float s_f;

    const int tid = threadIdx.x;
    const int i = tid >> 5, jj = tid & 31;
    const float L2E = 1.4426950408889634f;

    // column jj of M = exp(trans) in registers
    float Mreg[32];
    #pragma unroll
    for (int k = 0; k < 32; k++)
        Mreg[k] = exp2f(__ldg(&trans[k * NTAGS + jj]) * L2E);

    const int c  = blockIdx.x;
    const int t0 = (c == 0) ? 1 : c * CHUNK;
    const int t1 = (c + 1) * CHUNK;

    A[0][i][jj] = (i == jj) ? 1.f : 0.f;
    float L = 0.f;
    __syncthreads();

    int pb = 0;
    for (int t = t0; t < t1; t++) {
        float eemv = g_eem[t][jj];
        const float4* rowp = (const float4*)&A[pb][i][0];
        float acc = 0.f;
        #pragma unroll
        for (int q = 0; q < 8; q++) {
            float4 r4 = rowp[q];
            acc = fmaf(r4.x, Mreg[4 * q + 0], acc);
            acc = fmaf(r4.y, Mreg[4 * q + 1], acc);
            acc = fmaf(r4.z, Mreg[4 * q + 2], acc);
            acc = fmaf(r4.w, Mreg[4 * q + 3], acc);
        }
        acc *= eemv;
        if (tid == 0) s_f = acc;
        __syncthreads();
        float r;
        asm("rcp.approx.f32 %0, %1;" : "=f"(r) : "f"(s_f));
        A[pb ^ 1][i][jj] = acc * r;
        if (tid == 0) {
            float l2r;
            asm("lg2.approx.f32 %0, %1;" : "=f"(l2r) : "f"(r));
            L -= l2r;
        }
        pb ^= 1;
        __syncthreads();
    }

    g_chunk[c][i][jj] = A[pb][i][jj];
    if (tid == 0) g_chunkL[c] = L;
}

// ============================================================================
// Kernel D2: numerator + sequential combine of 64 chunk matrices + logZ.
// ============================================================================
__global__ void __launch_bounds__(1024, 1)
crf_final_kernel(const float* __restrict__ trans,
                 const float* __restrict__ start_trans,
                 const float* __restrict__ end_trans,
                 const int*   __restrict__ y,
                 float* __restrict__ out)
{
    __shared__ __align__(16) float R[NTAGS][36];
    __shared__ __align__(16) float B[NTAGS][36];
    __shared__ float s_num;
    __shared__ float s_red[32];
    __shared__ float s_f;
    __shared__ float sv0[NTAGS];

    const int tid = threadIdx.x;
    const int lane = tid & 31, warp = tid >> 5;
    const int i = tid >> 5, jj = tid & 31;

    const float L2E = 1.4426950408889634f;
    const float LN2 = 0.6931471805599453f;

    // ---- gold path score (numerator), 1024 threads ----
    float part = 0.f;
    for (int t = tid; t < SEQ; t += 1024) {
        int yt = y[t];
        part += g_em[t][yt];
        if (t > 0) part += trans[y[t - 1] * NTAGS + yt];
    }
    #pragma unroll
    for (int o = 16; o; o >>= 1) part += __shfl_xor_sync(~0u, part, o);
    if (lane == 0) s_red[warp] = part;
    __syncthreads();
    if (tid == 0) {
        float num = start_trans[y[0]] + end_trans[y[SEQ - 1]];
        #pragma unroll
        for (int wv = 0; wv < 32; wv++) num += s_red[wv];
        s_num = num;
    }

    // ---- combine: Rtot = C_0 * C_1 * ... * C_63, renorm each product ----
    R[i][jj] = g_chunk[0][i][jj];
    float L = 0.f;
    if (tid == 0) {
        #pragma unroll
        for (int cc = 0; cc < NCHUNK; cc++) L += g_chunkL[cc];
    }
    __syncthreads();

    for (int c = 1; c < NCHUNK; c++) {
        B[i][jj] = g_chunk[c][i][jj];
        __syncthreads();
        const float4* rowp = (const float4*)&R[i][0];
        float acc = 0.f;
        #pragma unroll
        for (int q = 0; q < 8; q++) {
            float4 r4 = rowp[q];
            acc = fmaf(r4.x, B[4 * q + 0][jj], acc);
            acc = fmaf(r4.y, B[4 * q + 1][jj], acc);
            acc = fmaf(r4.z, B[4 * q + 2][jj], acc);
            acc = fmaf(r4.w, B[4 * q + 3][jj], acc);
        }
        if (tid == 0) s_f = acc;
        __syncthreads();
        float r;
        asm("rcp.approx.f32 %0, %1;" : "=f"(r) : "f"(s_f));
        R[i][jj] = acc * r;
        if (tid == 0) {
            float l2r;
            asm("lg2.approx.f32 %0, %1;" : "=f"(l2r) : "f"(r));
            L -= l2r;
        }
        __syncthreads();
    }

    // ---- alpha0 fold-in + end, warp 0 ----
    if (warp == 0) {
        sv0[lane] = exp2f((start_trans[lane] + g_em[0][lane]) * L2E);
        __syncwarp();
        float acc = 0.f;
        #pragma unroll
        for (int k = 0; k < 32; k++)
            acc = fmaf(sv0[k], R[k][lane], acc);
        float term = acc * exp2f(end_trans[lane] * L2E);
        #pragma unroll
        for (int o = 16; o; o >>= 1) term += __shfl_xor_sync(~0u, term, o);
        if (lane == 0) {
            float l2S;
            asm("lg2.approx.f32 %0, %1;" : "=f"(l2S) : "f"(term));
            out[0] = (l2S + L) * LN2 - s_num;
        }
    }
}

// ============================================================================
extern "C" void kernel_launch(void* const* d_in, const int* in_sizes, int n_in,
                              void* d_out, int out_size)
{
    const float* embed       = (const float*)d_in[0];
    const float* w_ih_f      = (const float*)d_in[1];
    const float* w_hh_f      = (const float*)d_in[2];
    const float* b_ih_f      = (const float*)d_in[3];
    const float* b_hh_f      = (const float*)d_in[4];
    const float* w_ih_b      = (const float*)d_in[5];
    const float* w_hh_b      = (const float*)d_in[6];
    const float* b_ih_b      = (const float*)d_in[7];
    const float* b_hh_b      = (const float*)d_in[8];
    const float* w_lin       = (const float*)d_in[9];
    const float* b_lin       = (const float*)d_in[10];
    const float* trans       = (const float*)d_in[11];
    const float* start_trans = (const float*)d_in[12];
    const float* end_trans   = (const float*)d_in[13];
    const int*   x           = (const int*)d_in[14];
    const int*   y           = (const int*)d_in[15];

    dim3 gA(SEQ / 64, G4 / 64, 2);
    gx_kernel<<<gA, 256>>>(embed, w_ih_f, b_ih_f, b_hh_f,
                           w_ih_b, b_ih_b, b_hh_b, x);
    lstm_kernel<<<16, 512>>>(w_hh_f, w_hh_b);
    emis_kernel<<<SEQ, 512>>>(w_lin, b_lin);
    crf_chunk_kernel<<<NCHUNK, 1024>>>(trans);
    crf_final_kernel<<<1, 1024>>>(trans, start_trans, end_trans, y,
                                  (float*)d_out);
}

// round 17
// speedup vs baseline: 1.0935x; 1.0586x over previous
#include <cuda_runtime.h>
#include <cstdint>
#include <math.h>

#define SEQ   4096
#define EMB   256
#define H     256
#define G4    1024   // 4*H
#define NTAGS 32
#define NCHUNK 64
#define CHUNK  64

// ---------------- scratch (device globals: no allocation allowed) ----------
__device__ float g_gx[2][SEQ][G4];       // input projections per direction
__device__ float g_hs[SEQ][2 * H];       // concatenated BiLSTM hidden states
__device__ float g_em[SEQ][NTAGS];       // emissions (log space)
__device__ float g_chunk[NCHUNK][NTAGS][NTAGS];  // chunk transfer matrices
__device__ float g_chunkL[NCHUNK];               // their log2 scale factors

__device__ __forceinline__ unsigned smem_u32(const void* p) {
    return (unsigned)__cvta_generic_to_shared(p);
}

#define CLUSTER_ARRIVE() \
    asm volatile("barrier.cluster.arrive.aligned;" ::: "memory")
#define CLUSTER_WAIT() \
    asm volatile("barrier.cluster.wait.aligned;"   ::: "memory")
#define CLUSTER_SYNC_ASM() do { CLUSTER_ARRIVE(); CLUSTER_WAIT(); } while (0)

#define FFMA2(acc, a, b) \
    asm("fma.rn.f32x2 %0, %1, %2, %0;" : "+l"(acc) : "l"(a), "l"(b))

// ============================================================================
// Kernel A: gx[d][t][r] = emb_d[t] . w_ih_d[r] + b_ih[r] + b_hh[r]
// 64x64 tiles, BK=32, f32x2 inner product (K-paired accumulators).
// ============================================================================
__global__ void __launch_bounds__(256, 1)
gx_kernel(const float* __restrict__ embed,
          const float* __restrict__ w_ih_f,
          const float* __restrict__ b_ih_f,
          const float* __restrict__ b_hh_f,
          const float* __restrict__ w_ih_b,
          const float* __restrict__ b_ih_b,
          const float* __restrict__ b_hh_b,
          const int*   __restrict__ x)
{
    const int dir = blockIdx.z;
    const float* w_ih = dir ? w_ih_b : w_ih_f;
    const float* b_ih = dir ? b_ih_b : b_ih_f;
    const float* b_hh = dir ? b_hh_b : b_hh_f;

    __shared__ unsigned long long As2[64][17];
    __shared__ unsigned long long Bs2[64][17];
    __shared__ int toks[64];

    const int tid = threadIdx.x;
    const int t0 = blockIdx.x * 64;
    const int r0 = blockIdx.y * 64;

    if (tid < 64) {
        int t = t0 + tid;
        int p = dir ? (SEQ - 1 - t) : t;
        toks[tid] = x[p];
    }
    __syncthreads();

    const int tx = tid & 15, ty = tid >> 4;
    unsigned long long c2[4][4];
    #pragma unroll
    for (int u = 0; u < 4; u++)
        #pragma unroll
        for (int v = 0; v < 4; v++) c2[u][v] = 0ull;

    for (int k0 = 0; k0 < EMB; k0 += 32) {
        #pragma unroll
        for (int i = tid; i < 64 * 16; i += 256) {
            int row = i >> 4, k2 = i & 15;
            As2[row][k2] = *(const unsigned long long*)
                &embed[(size_t)toks[row] * EMB + k0 + 2 * k2];
        }
        #pragma unroll
        for (int i = tid; i < 64 * 16; i += 256) {
            int row = i >> 4, k2 = i & 15;
            Bs2[row][k2] = *(const unsigned long long*)
                &w_ih[(size_t)(r0 + row) * EMB + k0 + 2 * k2];
        }
        __syncthreads();
        #pragma unroll
        for (int k2 = 0; k2 < 16; k2++) {
            unsigned long long a2[4], b2[4];
            #pragma unroll
            for (int u = 0; u < 4; u++) a2[u] = As2[ty + 16 * u][k2];
            #pragma unroll
            for (int v = 0; v < 4; v++) b2[v] = Bs2[tx + 16 * v][k2];
            #pragma unroll
            for (int u = 0; u < 4; u++)
                #pragma unroll
                for (int v = 0; v < 4; v++)
                    FFMA2(c2[u][v], a2[u], b2[v]);
        }
        __syncthreads();
    }

    #pragma unroll
    for (int u = 0; u < 4; u++) {
        int t = t0 + ty + 16 * u;
        #pragma unroll
        for (int v = 0; v < 4; v++) {
            int r = r0 + tx + 16 * v;
            float lo, hi;
            asm("mov.b64 {%0,%1}, %2;" : "=f"(lo), "=f"(hi) : "l"(c2[u][v]));
            g_gx[dir][t][r] = (lo + hi) + b_ih[r] + b_hh[r];
        }
    }
}

// ============================================================================
// Kernel B: sequential BiLSTM recurrence (2 clusters of 8 CTAs).
// EXACT r12 proven config: warp-uniform K slice, red[s*128+g] stride-1
// reduction, f32x2 matvec with register weights, warp-0 tail (ex2/rcp),
// register raddr double buffer, HW cluster barrier split arrive/wait,
// one-step-ahead gx prefetch.  (Tail-split r16 and all software syncs
// measured neutral-or-worse; this is the plateau config.)
// ============================================================================
__global__ void __cluster_dims__(8, 1, 1) __launch_bounds__(512, 1)
lstm_kernel(const float* __restrict__ w_hh_f, const float* __restrict__ w_hh_b)
{
    __shared__ __align__(16) float sh_h[2][256];   // double-buffered h
    __shared__ float red[512];

    const int tid = threadIdx.x;
    const int dir = blockIdx.x >> 3;
    unsigned rank;
    asm("mov.u32 %0, %%cluster_ctarank;" : "=r"(rank));
    const int j0 = (int)rank * 32;

    const float* __restrict__ w_hh = dir ? w_hh_b : w_hh_f;

    const int g    = ((tid >> 7) << 5) | (tid & 31);  // 0..127 local gate id
    const int s    = (tid >> 5) & 3;                  // 0..3  K slice
    const int gate = g >> 5;                          // i,f,g,o
    const int j    = g & 31;                          // hidden index within CTA
    const int row  = gate * H + j0 + j;               // global gate row

    // ---- weights into registers as packed f32x2 pairs ----
    unsigned long long w2[32];
    {
        const ulonglong2* wv =
            (const ulonglong2*)(w_hh + (size_t)row * H + s * 64);
        #pragma unroll
        for (int q = 0; q < 16; q++) {
            ulonglong2 v = wv[q];
            w2[2 * q] = v.x; w2[2 * q + 1] = v.y;
        }
    }

    if (tid < 256) { sh_h[0][tid] = 0.f; sh_h[1][tid] = 0.f; }

    // remote h addresses in two separate register arrays (no LDL)
    unsigned raddr0[8], raddr1[8];
    if (tid < 32) {
        unsigned la0 = smem_u32(&sh_h[0][j0 + tid]);
        unsigned la1 = smem_u32(&sh_h[1][j0 + tid]);
        #pragma unroll
        for (int cc = 0; cc < 8; cc++) {
            asm("mapa.shared::cluster.u32 %0, %1, %2;"
                : "=r"(raddr0[cc]) : "r"(la0), "r"(cc));
            asm("mapa.shared::cluster.u32 %0, %1, %2;"
                : "=r"(raddr1[cc]) : "r"(la1), "r"(cc));
        }
    }

    CLUSTER_SYNC_ASM();   // zeros visible cluster-wide

    float cstate = 0.f;
    const float* __restrict__ gx_base = &g_gx[dir][0][0];
    const float L2E = 1.4426950408889634f;

    // preload gx for step 0
    float gc0 = 0.f, gc1 = 0.f, gc2 = 0.f, gc3 = 0.f;
    if (tid < 32) {
        const float* p = gx_base + j0 + tid;
        gc0 = __ldg(p + 0 * H); gc1 = __ldg(p + 1 * H);
        gc2 = __ldg(p + 2 * H); gc3 = __ldg(p + 3 * H);
    }

    for (int step = 0; step < SEQ; step++) {
        // prefetch NEXT step's gx (full-step DRAM-latency cover)
        float gn0 = 0.f, gn1 = 0.f, gn2 = 0.f, gn3 = 0.f;
        if (tid < 32 && step + 1 < SEQ) {
            const float* p = gx_base + (size_t)(step + 1) * G4 + j0 + tid;
            gn0 = __ldg(p + 0 * H); gn1 = __ldg(p + 1 * H);
            gn2 = __ldg(p + 2 * H); gn3 = __ldg(p + 3 * H);
        }

        if (step > 0) CLUSTER_WAIT();   // h_{t-1} remote stores published
        const int rb = step & 1, wb = rb ^ 1;

        // ---- phase 1: partial dot over this thread's 64-wide K slice ----
        const ulonglong2* hv = (const ulonglong2*)&sh_h[rb][s * 64];
        unsigned long long acc0 = 0ull, acc1 = 0ull;
        #pragma unroll
        for (int q = 0; q < 16; q++) {
            ulonglong2 h2 = hv[q];
            FFMA2(acc0, w2[2 * q],     h2.x);
            FFMA2(acc1, w2[2 * q + 1], h2.y);
        }
        float lo0, hi0, lo1, hi1;
        asm("mov.b64 {%0,%1}, %2;" : "=f"(lo0), "=f"(hi0) : "l"(acc0));
        asm("mov.b64 {%0,%1}, %2;" : "=f"(lo1), "=f"(hi1) : "l"(acc1));
        red[s * 128 + g] = (lo0 + hi0) + (lo1 + hi1);   // stride-1: no conflicts
        __syncthreads();

        // ---- phase 2: warp 0 finishes gates, cell update, broadcast ----
        if (tid < 32) {
            float gi = gc0, gf = gc1, gg = gc2, go = gc3;
            #pragma unroll
            for (int sl = 0; sl < 4; sl++) {
                gi += red[sl * 128 + 0 * 32 + tid];
                gf += red[sl * 128 + 1 * 32 + tid];
                gg += red[sl * 128 + 2 * 32 + tid];
                go += red[sl * 128 + 3 * 32 + tid];
            }
            float ei, ef, eg, eo, iv, fv, gv, ov;
            asm("ex2.approx.f32 %0, %1;" : "=f"(ei) : "f"(-L2E * gi));
            asm("ex2.approx.f32 %0, %1;" : "=f"(ef) : "f"(-L2E * gf));
            asm("ex2.approx.f32 %0, %1;" : "=f"(eg) : "f"(-2.f * L2E * gg));
            asm("ex2.approx.f32 %0, %1;" : "=f"(eo) : "f"(-L2E * go));
            asm("rcp.approx.f32 %0, %1;" : "=f"(iv) : "f"(1.f + ei));
            asm("rcp.approx.f32 %0, %1;" : "=f"(fv) : "f"(1.f + ef));
            asm("rcp.approx.f32 %0, %1;" : "=f"(gv) : "f"(1.f + eg));
            asm("rcp.approx.f32 %0, %1;" : "=f"(ov) : "f"(1.f + eo));
            gv = 2.f * gv - 1.f;                     // tanh(gg)
            cstate = fv * cstate + iv * gv;
            float ec, rc;
            asm("ex2.approx.f32 %0, %1;" : "=f"(ec) : "f"(-2.f * L2E * cstate));
            asm("rcp.approx.f32 %0, %1;" : "=f"(rc) : "f"(1.f + ec));
            float h = ov * (2.f * rc - 1.f);

            #pragma unroll
            for (int cc = 0; cc < 8; cc++) {
                unsigned ad = wb ? raddr1[cc] : raddr0[cc];
                asm volatile("st.shared::cluster.f32 [%0], %1;"
                             :: "r"(ad), "f"(h));
            }
            int pos = dir ? (SEQ - 1 - step) : step;
            g_hs[pos][dir * H + j0 + tid] = h;

            gc0 = gn0; gc1 = gn1; gc2 = gn2; gc3 = gn3;
        }
        CLUSTER_ARRIVE();   // release: publishes this step's remote h stores
    }
    CLUSTER_WAIT();         // match final arrives; smem alive until all landed
}

// ============================================================================
// Kernel D1: FUSED emissions + CRF chunk transfer matrices (64 blocks).
// Phase A: block c computes em[t] = hs[t].w_lin^T + b_lin for its 64
//   timesteps (32 passes x 2 t; per-thread w_lin slice in REGISTERS, loaded
//   once — the standalone emis kernel's strided w_lin reads cost ~2GB of L2
//   traffic), writes g_em (numerator) and exp2-space eem into SMEM.
// Phase B: C_c = prod_t (M ∘ colscale(eem_t)), per-step renorm by C[0][0],
//   applied factor tracked exactly in log2 (true product = 2^L . stored).
// ============================================================================
__global__ void __launch_bounds__(1024, 1)
crf_chunk_kernel(const float* __restrict__ trans,
                 const float* __restrict__ w_lin,
                 const float* __restrict__ b_lin)
{
    __shared__ __align__(16) float hsm[2][512];
    __shared__ float redc[1024];
    __shared__ float eem_sm[CHUNK][NTAGS];
    __shared__ __align__(16) float A[2][NTAGS][36];   // 36: 16B-aligned rows
    __shared__ float s_f;

    const int tid = threadIdx.x;
    const int c   = blockIdx.x;
    const int t0c = c * CHUNK;
    const float L2E = 1.4426950408889634f;

    // ---------------- phase A: emissions for t0c .. t0c+63 ----------------
    {
        const int t2  = tid >> 9;        // which of the 2 timesteps per pass
        const int rr  = tid & 511;
        const int ka  = rr & 31;         // tag
        const int sla = rr >> 5;         // 32-wide slice of the 512 hidden

        // per-thread w_lin slice (constant across passes) as f32x2 pairs
        unsigned long long w2r[16];
        {
            const unsigned long long* wp = (const unsigned long long*)
                &w_lin[(size_t)ka * 512 + sla * 32];
            #pragma unroll
            for (int q = 0; q < 16; q++) w2r[q] = __ldg(wp + q);
        }

        for (int pass = 0; pass < 32; pass++) {
            ((float*)hsm)[tid] =
                g_hs[t0c + pass * 2 + (tid >> 9)][tid & 511];
            __syncthreads();

            const unsigned long long* hp =
                (const unsigned long long*)&hsm[t2][sla * 32];
            unsigned long long acc = 0ull;
            #pragma unroll
            for (int q = 0; q < 16; q++) FFMA2(acc, w2r[q], hp[q]);
            float lo, hi;
            asm("mov.b64 {%0,%1}, %2;" : "=f"(lo), "=f"(hi) : "l"(acc));
            redc[tid] = lo + hi;
            __syncthreads();

            if (tid < 64) {
                int t2r = tid >> 5, kr = tid & 31;
                float sum = __ldg(&b_lin[kr]);
                #pragma unroll
                for (int q = 0; q < 16; q++)
                    sum += redc[t2r * 512 + q * 32 + kr];
                int tt = t0c + pass * 2 + t2r;
                g_em[tt][kr] = sum;
                eem_sm[pass * 2 + t2r][kr] = exp2f(sum * L2E);
            }
            __syncthreads();
        }
    }

    // ---------------- phase B: chunk transfer matrix ----------------
    const int i = tid >> 5, jj = tid & 31;

    // column jj of M = exp(trans) in registers (loaded after phase A so the
    // w2r registers are dead first)
    float Mreg[32];
    #pragma unroll
    for (int k = 0; k < 32; k++)
        Mreg[k] = exp2f(__ldg(&trans[k * NTAGS + jj]) * L2E);

    const int t0 = (c == 0) ? 1 : t0c;
    const int t1 = t0c + CHUNK;

    A[0][i][jj] = (i == jj) ? 1.f : 0.f;
    float L = 0.f;
    __syncthreads();

    int pb = 0;
    for (int t = t0; t < t1; t++) {
        float eemv = eem_sm[t - t0c][jj];
        const float4* rowp = (const float4*)&A[pb][i][0];
        float acc = 0.f;
        #pragma unroll
        for (int q = 0; q < 8; q++) {
            float4 r4 = rowp[q];
            acc = fmaf(r4.x, Mreg[4 * q + 0], acc);
            acc = fmaf(r4.y, Mreg[4 * q + 1], acc);
            acc = fmaf(r4.z, Mreg[4 * q + 2], acc);
            acc = fmaf(r4.w, Mreg[4 * q + 3], acc);
        }
        acc *= eemv;
        if (tid == 0) s_f = acc;
        __syncthreads();
        float r;
        asm("rcp.approx.f32 %0, %1;" : "=f"(r) : "f"(s_f));
        A[pb ^ 1][i][jj] = acc * r;
        if (tid == 0) {
            float l2r;
            asm("lg2.approx.f32 %0, %1;" : "=f"(l2r) : "f"(r));
            L -= l2r;
        }
        pb ^= 1;
        __syncthreads();
    }

    g_chunk[c][i][jj] = A[pb][i][jj];
    if (tid == 0) g_chunkL[c] = L;
}

// ============================================================================
// Kernel D2: numerator + sequential combine of 64 chunk matrices + logZ.
// ============================================================================
__global__ void __launch_bounds__(1024, 1)
crf_final_kernel(const float* __restrict__ trans,
                 const float* __restrict__ start_trans,
                 const float* __restrict__ end_trans,
                 const int*   __restrict__ y,
                 float* __restrict__ out)
{
    __shared__ __align__(16) float R[NTAGS][36];
    __shared__ __align__(16) float B[NTAGS][36];
    __shared__ float s_num;
    __shared__ float s_red[32];
    __shared__ float s_f;
    __shared__ float sv0[NTAGS];

    const int tid = threadIdx.x;
    const int lane = tid & 31, warp = tid >> 5;
    const int i = tid >> 5, jj = tid & 31;

    const float L2E = 1.4426950408889634f;
    const float LN2 = 0.6931471805599453f;

    // ---- gold path score (numerator), 1024 threads ----
    float part = 0.f;
    for (int t = tid; t < SEQ; t += 1024) {
        int yt = y[t];
        part += g_em[t][yt];
        if (t > 0) part += trans[y[t - 1] * NTAGS + yt];
    }
    #pragma unroll
    for (int o = 16; o; o >>= 1) part += __shfl_xor_sync(~0u, part, o);
    if (lane == 0) s_red[warp] = part;
    __syncthreads();
    if (tid == 0) {
        float num = start_trans[y[0]] + end_trans[y[SEQ - 1]];
        #pragma unroll
        for (int wv = 0; wv < 32; wv++) num += s_red[wv];
        s_num = num;
    }

    // ---- combine: Rtot = C_0 * C_1 * ... * C_63, renorm each product ----
    R[i][jj] = g_chunk[0][i][jj];
    float L = 0.f;
    if (tid == 0) {
        #pragma unroll
        for (int cc = 0; cc < NCHUNK; cc++) L += g_chunkL[cc];
    }
    __syncthreads();

    for (int c = 1; c < NCHUNK; c++) {
        B[i][jj] = g_chunk[c][i][jj];
        __syncthreads();
        const float4* rowp = (const float4*)&R[i][0];
        float acc = 0.f;
        #pragma unroll
        for (int q = 0; q < 8; q++) {
            float4 r4 = rowp[q];
            acc = fmaf(r4.x, B[4 * q + 0][jj], acc);
            acc = fmaf(r4.y, B[4 * q + 1][jj], acc);
            acc = fmaf(r4.z, B[4 * q + 2][jj], acc);
            acc = fmaf(r4.w, B[4 * q + 3][jj], acc);
        }
        if (tid == 0) s_f = acc;
        __syncthreads();
        float r;
        asm("rcp.approx.f32 %0, %1;" : "=f"(r) : "f"(s_f));
        R[i][jj] = acc * r;
        if (tid == 0) {
            float l2r;
            asm("lg2.approx.f32 %0, %1;" : "=f"(l2r) : "f"(r));
            L -= l2r;
        }
        __syncthreads();
    }

    // ---- alpha0 fold-in + end, warp 0 ----
    if (warp == 0) {
        sv0[lane] = exp2f((start_trans[lane] + g_em[0][lane]) * L2E);
        __syncwarp();
        float acc = 0.f;
        #pragma unroll
        for (int k = 0; k < 32; k++)
            acc = fmaf(sv0[k], R[k][lane], acc);
        float term = acc * exp2f(end_trans[lane] * L2E);
        #pragma unroll
        for (int o = 16; o; o >>= 1) term += __shfl_xor_sync(~0u, term, o);
        if (lane == 0) {
            float l2S;
            asm("lg2.approx.f32 %0, %1;" : "=f"(l2S) : "f"(term));
            out[0] = (l2S + L) * LN2 - s_num;
        }
    }
}

// ============================================================================
extern "C" void kernel_launch(void* const* d_in, const int* in_sizes, int n_in,
                              void* d_out, int out_size)
{
    const float* embed       = (const float*)d_in[0];
    const float* w_ih_f      = (const float*)d_in[1];
    const float* w_hh_f      = (const float*)d_in[2];
    const float* b_ih_f      = (const float*)d_in[3];
    const float* b_hh_f      = (const float*)d_in[4];
    const float* w_ih_b      = (const float*)d_in[5];
    const float* w_hh_b      = (const float*)d_in[6];
    const float* b_ih_b      = (const float*)d_in[7];
    const float* b_hh_b      = (const float*)d_in[8];
    const float* w_lin       = (const float*)d_in[9];
    const float* b_lin       = (const float*)d_in[10];
    const float* trans       = (const float*)d_in[11];
    const float* start_trans = (const float*)d_in[12];
    const float* end_trans   = (const float*)d_in[13];
    const int*   x           = (const int*)d_in[14];
    const int*   y           = (const int*)d_in[15];

    dim3 gA(SEQ / 64, G4 / 64, 2);
    gx_kernel<<<gA, 256>>>(embed, w_ih_f, b_ih_f, b_hh_f,
                           w_ih_b, b_ih_b, b_hh_b, x);
    lstm_kernel<<<16, 512>>>(w_hh_f, w_hh_b);
    crf_chunk_kernel<<<NCHUNK, 1024>>>(trans, w_lin, b_lin);
    crf_final_kernel<<<1, 1024>>>(trans, start_trans, end_trans, y,
                                  (float*)d_out);
}